// round 7
// baseline (speedup 1.0000x reference)
#include <cuda_runtime.h>
#include <cuda_bf16.h>
#include <mma.h>
#include <cstdint>

using namespace nvcuda;

#define OBS 194
#define HID 64
#define NACT 5
#define TM 128

// ---------------- SMEM layout (bytes) ----------------
// Phase A (GEMM1): B1HI/B1LO resident, AC chunk buffers
// Phase B (epi1/GEMM2): B1 region reused for CSCR + A2HI/A2LO
// Phase C (epi2/head): B1 region reused for C2 (float)
#define B1HI_OFF 0                    // 208*136*2 = 56576
#define B1LO_OFF 56576                // 56576
#define CSCR_OFF 0                    // 128*68*4  = 34816 (reuse)
#define A2HI_OFF 36864                // 128*136*2 = 34816 (reuse)
#define A2LO_OFF 73728                // 34816 (reuse)  end 108544 <= 113152
#define C2_OFF   0                    // 128*132*4 = 67584 (reuse)
#define B2HI_OFF 113152               // 128*136*2 = 34816
#define B2LO_OFF 147968               // 34816
#define ACHI_OFF 182784               // 128*72*2 = 18432
#define ACLO_OFF 201216               // 18432 -> 219648
#define WHS_OFF  219648               // 960 floats = 3840
#define B1S_OFF  223488               // 128 floats
#define B2S_OFF  224000               // 128 floats
#define WC3S_OFF 224512               // 64 floats
#define BHS_OFF  224768               // 16 floats
#define BC3S_OFF 224832               // 1 float
#define SMEM_BYTES 224848

#define LDB1 136
#define LDB2 136
#define LDAC 72
#define LDA2 136
#define LDCS 68
#define LDC2 132

static __device__ __forceinline__ float tanh_fast(float x) {
    float y;
    asm("tanh.approx.f32 %0, %1;" : "=f"(y) : "f"(x));
    return y;
}
static __device__ __forceinline__ void split2(float v, __nv_bfloat16& h, __nv_bfloat16& l) {
    h = __float2bfloat16(v);
    l = __float2bfloat16(v - __bfloat162float(h));
}

__global__ void __launch_bounds__(256, 1)
agent_wmma_kernel(const float* __restrict__ x, const int* __restrict__ action,
                  const float* __restrict__ W1, const float* __restrict__ b1,
                  const float* __restrict__ W2, const float* __restrict__ b2,
                  const float* __restrict__ Wh, const float* __restrict__ bh,
                  const float* __restrict__ Wc1, const float* __restrict__ bc1,
                  const float* __restrict__ Wc2, const float* __restrict__ bc2,
                  const float* __restrict__ Wc3, const float* __restrict__ bc3,
                  float* __restrict__ out, int B)
{
    extern __shared__ char smem[];
    const int tid  = threadIdx.x;
    const int wid  = tid >> 5;
    const int b0   = blockIdx.x * TM;

    __nv_bfloat16* b1hi = (__nv_bfloat16*)(smem + B1HI_OFF);
    __nv_bfloat16* b1lo = (__nv_bfloat16*)(smem + B1LO_OFF);
    __nv_bfloat16* b2hi = (__nv_bfloat16*)(smem + B2HI_OFF);
    __nv_bfloat16* b2lo = (__nv_bfloat16*)(smem + B2LO_OFF);
    __nv_bfloat16* achi = (__nv_bfloat16*)(smem + ACHI_OFF);
    __nv_bfloat16* aclo = (__nv_bfloat16*)(smem + ACLO_OFF);
    __nv_bfloat16* a2hi = (__nv_bfloat16*)(smem + A2HI_OFF);
    __nv_bfloat16* a2lo = (__nv_bfloat16*)(smem + A2LO_OFF);
    float* cscr = (float*)(smem + CSCR_OFF);
    float* c2   = (float*)(smem + C2_OFF);
    float* whs  = (float*)(smem + WHS_OFF);
    float* b1s  = (float*)(smem + B1S_OFF);
    float* b2s  = (float*)(smem + B2S_OFF);
    float* wc3s = (float*)(smem + WC3S_OFF);
    float* bhs  = (float*)(smem + BHS_OFF);
    float* bc3s = (float*)(smem + BC3S_OFF);

    // ---- stage B1 = [W1 | Wc1] as [K=208][N=128] bf16 hi/lo, ld 136 ----
    for (int i = tid; i < 208 * 128; i += 256) {
        int k = i >> 7, n = i & 127;
        float v = 0.f;
        if (k < OBS) v = (n < 64) ? W1[k * 64 + n] : Wc1[k * 64 + (n - 64)];
        __nv_bfloat16 h, l; split2(v, h, l);
        b1hi[k * LDB1 + n] = h;
        b1lo[k * LDB1 + n] = l;
    }
    // ---- stage B2 block-diag [W2 ; Wc2] as [K=128][N=128] bf16 hi/lo ----
    for (int i = tid; i < 128 * 128; i += 256) {
        int k = i >> 7, n = i & 127;
        float v = 0.f;
        if (k < 64 && n < 64)        v = W2[k * 64 + n];
        else if (k >= 64 && n >= 64) v = Wc2[(k - 64) * 64 + (n - 64)];
        __nv_bfloat16 h, l; split2(v, h, l);
        b2hi[k * LDB2 + n] = h;
        b2lo[k * LDB2 + n] = l;
    }
    if (tid < 64) {
        b1s[tid] = b1[tid];  b1s[64 + tid] = bc1[tid];
        b2s[tid] = b2[tid];  b2s[64 + tid] = bc2[tid];
        wc3s[tid] = Wc3[tid];
    }
    for (int i = tid; i < 3 * HID * NACT; i += 256) whs[i] = Wh[i];
    if (tid < 3 * NACT) bhs[tid] = bh[tid];
    if (tid == 0) bc3s[0] = bc3[0];

    // ---- prefetch x chunk 0 (K cols 0..63) ----
    float v[32];
    {
        #pragma unroll
        for (int t = 0; t < 32; t++) {
            int i = t * 256 + tid;
            int row = i >> 6, col = i & 63;
            int gb = b0 + row;
            v[t] = (gb < B && col < OBS) ? x[(size_t)gb * OBS + col] : 0.f;
        }
    }
    __syncthreads();    // B staging complete
    // store chunk 0
    #pragma unroll
    for (int t = 0; t < 32; t++) {
        int i = t * 256 + tid;
        int row = i >> 6, col = i & 63;
        __nv_bfloat16 h, l; split2(v[t], h, l);
        achi[row * LDAC + col] = h;
        aclo[row * LDAC + col] = l;
    }

    // ---- GEMM1: acc[128x128] = Xsplit[128x208] @ B1[208x128], 3-term bf16 split ----
    wmma::fragment<wmma::accumulator, 16, 16, 16, float> acc[8];
    #pragma unroll
    for (int j = 0; j < 8; j++) wmma::fill_fragment(acc[j], 0.0f);

    const int wrow = wid * 16;

    for (int ch = 0; ch < 4; ch++) {
        __syncthreads();    // chunk staged / previous compute done
        // prefetch next chunk
        if (ch < 3) {
            const int k0n = (ch + 1) * 64;
            if (ch < 2) {   // next is a full 64-col chunk
                #pragma unroll
                for (int t = 0; t < 32; t++) {
                    int i = t * 256 + tid;
                    int row = i >> 6, col = i & 63;
                    int gk = k0n + col, gb = b0 + row;
                    v[t] = (gb < B && gk < OBS) ? x[(size_t)gb * OBS + gk] : 0.f;
                }
            } else {        // next is the 16-col tail chunk
                #pragma unroll
                for (int t = 0; t < 8; t++) {
                    int i = t * 256 + tid;
                    int row = i >> 4, col = i & 15;
                    int gk = k0n + col, gb = b0 + row;
                    v[t] = (gb < B && gk < OBS) ? x[(size_t)gb * OBS + gk] : 0.f;
                }
            }
        }
        // compute current chunk
        {
            const int nkt = (ch == 3) ? 1 : 4;
            const int k0  = ch * 64;
            wmma::fragment<wmma::matrix_a, 16, 16, 16, __nv_bfloat16, wmma::row_major> af;
            wmma::fragment<wmma::matrix_b, 16, 16, 16, __nv_bfloat16, wmma::row_major> bf;
            #pragma unroll
            for (int p = 0; p < 3; p++) {
                const __nv_bfloat16* As = (p < 2) ? achi : aclo;
                const __nv_bfloat16* Bs = (p == 1) ? b1lo : b1hi;
                for (int kt = 0; kt < nkt; kt++) {
                    wmma::load_matrix_sync(af, As + wrow * LDAC + kt * 16, LDAC);
                    #pragma unroll
                    for (int j = 0; j < 8; j++) {
                        wmma::load_matrix_sync(bf, Bs + (k0 + kt * 16) * LDB1 + j * 16, LDB1);
                        wmma::mma_sync(acc[j], af, bf, acc[j]);
                    }
                }
            }
        }
        __syncthreads();    // compute done before restage
        if (ch < 3) {
            if (ch < 2) {
                #pragma unroll
                for (int t = 0; t < 32; t++) {
                    int i = t * 256 + tid;
                    int row = i >> 6, col = i & 63;
                    __nv_bfloat16 h, l; split2(v[t], h, l);
                    achi[row * LDAC + col] = h;
                    aclo[row * LDAC + col] = l;
                }
            } else {
                #pragma unroll
                for (int t = 0; t < 8; t++) {
                    int i = t * 256 + tid;
                    int row = i >> 4, col = i & 15;
                    __nv_bfloat16 h, l; split2(v[t], h, l);
                    achi[row * LDAC + col] = h;
                    aclo[row * LDAC + col] = l;
                }
            }
        }
    }
    __syncthreads();    // GEMM1 done; B1 region now reusable

    // ---- epilogue1: h1 = tanh(C1 + bias1) -> A2 bf16 hi/lo (two half-passes) ----
    #pragma unroll
    for (int h = 0; h < 2; h++) {
        #pragma unroll
        for (int jj = 0; jj < 4; jj++)
            wmma::store_matrix_sync(cscr + wrow * LDCS + jj * 16, acc[h * 4 + jj], LDCS, wmma::mem_row_major);
        __syncthreads();
        for (int i = tid; i < 128 * 64; i += 256) {
            int row = i >> 6, c = i & 63;
            int col = h * 64 + c;
            float f = tanh_fast(cscr[row * LDCS + c] + b1s[col]);
            __nv_bfloat16 hh, ll; split2(f, hh, ll);
            a2hi[row * LDA2 + col] = hh;
            a2lo[row * LDA2 + col] = ll;
        }
        __syncthreads();
    }

    // ---- GEMM2: C2 = A2[128x128] @ B2[128x128] (block-diag, skip zero tiles) ----
    #pragma unroll
    for (int j = 0; j < 8; j++) wmma::fill_fragment(acc[j], 0.0f);
    {
        wmma::fragment<wmma::matrix_a, 16, 16, 16, __nv_bfloat16, wmma::row_major> af;
        wmma::fragment<wmma::matrix_b, 16, 16, 16, __nv_bfloat16, wmma::row_major> bf;
        #pragma unroll
        for (int p = 0; p < 3; p++) {
            const __nv_bfloat16* As = (p < 2) ? a2hi : a2lo;
            const __nv_bfloat16* Bs = (p == 1) ? b2lo : b2hi;
            #pragma unroll
            for (int kt = 0; kt < 8; kt++) {
                wmma::load_matrix_sync(af, As + wrow * LDA2 + kt * 16, LDA2);
                const int jbase = (kt >> 2) * 4;   // block-diagonal: only matching quadrant
                #pragma unroll
                for (int jj = 0; jj < 4; jj++) {
                    int j = jbase + jj;
                    wmma::load_matrix_sync(bf, Bs + kt * 16 * LDB2 + j * 16, LDB2);
                    wmma::mma_sync(acc[j], af, bf, acc[j]);
                }
            }
        }
    }
    __syncthreads();    // all warps done reading A2 before C2 overwrites region

    // ---- epilogue2: store raw C2 (float) ----
    #pragma unroll
    for (int j = 0; j < 8; j++)
        wmma::store_matrix_sync(c2 + wrow * LDC2 + j * 16, acc[j], LDC2, wmma::mem_row_major);
    __syncthreads();

    // ---- head: 2 threads per row, shuffle-reduce ----
    {
        const int r    = tid >> 1;
        const int pair = tid & 1;
        const int b    = b0 + r;
        const bool rv  = b < B;

        int ev = 0;
        if (rv) {
            const float* xr = x + (size_t)b * OBS;
            float x0 = xr[0], x1 = xr[1], x2 = xr[2];
            float bv = x0;
            if (x1 > bv) { ev = 1; bv = x1; }
            if (x2 > bv) ev = 2;
        }
        float lg0 = 0.f, lg1 = 0.f, lg2 = 0.f, lg3 = 0.f, lg4 = 0.f, vv = 0.f;
        const float* whp = whs + ev * (HID * NACT);
        const float* cr  = c2 + r * LDC2;
        #pragma unroll 4
        for (int c = 0; c < 32; c++) {
            int col = pair * 32 + c;
            float f  = tanhf(cr[col] + b2s[col]);
            const float* w = whp + col * NACT;
            lg0 += f * w[0]; lg1 += f * w[1]; lg2 += f * w[2];
            lg3 += f * w[3]; lg4 += f * w[4];
            float fc = tanhf(cr[64 + col] + b2s[64 + col]);
            vv += fc * wc3s[col];
        }
        lg0 += __shfl_xor_sync(0xffffffffu, lg0, 1);
        lg1 += __shfl_xor_sync(0xffffffffu, lg1, 1);
        lg2 += __shfl_xor_sync(0xffffffffu, lg2, 1);
        lg3 += __shfl_xor_sync(0xffffffffu, lg3, 1);
        lg4 += __shfl_xor_sync(0xffffffffu, lg4, 1);
        vv  += __shfl_xor_sync(0xffffffffu, vv, 1);

        if (pair == 0 && rv) {
            const float* bhp = bhs + ev * NACT;
            lg0 += bhp[0]; lg1 += bhp[1]; lg2 += bhp[2]; lg3 += bhp[3]; lg4 += bhp[4];
            float m = fmaxf(fmaxf(fmaxf(lg0, lg1), fmaxf(lg2, lg3)), lg4);
            float e0 = expf(lg0 - m), e1 = expf(lg1 - m), e2 = expf(lg2 - m);
            float e3 = expf(lg3 - m), e4 = expf(lg4 - m);
            float lse = logf(e0 + e1 + e2 + e3 + e4);
            float p0 = lg0 - m - lse, p1 = lg1 - m - lse, p2 = lg2 - m - lse;
            float p3 = lg3 - m - lse, p4 = lg4 - m - lse;
            float ent = -(expf(p0) * p0 + expf(p1) * p1 + expf(p2) * p2
                          + expf(p3) * p3 + expf(p4) * p4);
            int act = action[b];
            float logp = (act == 0) ? p0 : (act == 1) ? p1 : (act == 2) ? p2 : (act == 3) ? p3 : p4;
            out[b]                 = (float)act;
            out[(size_t)B + b]     = logp;
            out[(size_t)2 * B + b] = ent;
            out[(size_t)3 * B + b] = vv + bc3s[0];
        }
    }
}

extern "C" void kernel_launch(void* const* d_in, const int* in_sizes, int n_in,
                              void* d_out, int out_size)
{
    const float* x      = (const float*)d_in[0];
    const int*   action = (const int*)  d_in[1];
    const float* W1     = (const float*)d_in[2];
    const float* b1     = (const float*)d_in[3];
    const float* W2     = (const float*)d_in[4];
    const float* b2     = (const float*)d_in[5];
    const float* Wh     = (const float*)d_in[6];
    const float* bh     = (const float*)d_in[7];
    const float* Wc1    = (const float*)d_in[8];
    const float* bc1    = (const float*)d_in[9];
    const float* Wc2    = (const float*)d_in[10];
    const float* bc2    = (const float*)d_in[11];
    const float* Wc3    = (const float*)d_in[12];
    const float* bc3    = (const float*)d_in[13];
    float* out = (float*)d_out;

    const int B = in_sizes[1];
    (void)n_in; (void)out_size;

    cudaFuncSetAttribute(agent_wmma_kernel,
                         cudaFuncAttributeMaxDynamicSharedMemorySize, SMEM_BYTES);

    const int grid = (B + TM - 1) / TM;
    agent_wmma_kernel<<<grid, 256, SMEM_BYTES>>>(
        x, action, W1, b1, W2, b2, Wh, bh, Wc1, bc1, Wc2, bc2, Wc3, bc3, out, B);
}